// round 4
// baseline (speedup 1.0000x reference)
#include <cuda_runtime.h>

// Problem constants
#define NPTS   16384
#define NCHAN  64
#define DX     100
#define DY     88
#define DZ     80
#define PLANE  (DX*DY*DZ)          // 704000 floats per channel plane

// 8 threads per point, 8 channels per thread.
#define TPP    8
#define CPT    (NCHAN / TPP)       // 8
#define TPB    256
#define GRID   (NPTS * TPP / TPB)  // 512 blocks

__device__ float        g_partials[GRID];
__device__ unsigned int g_count = 0;

__device__ __forceinline__ int redirect(int v, int idx0, int m) {
    int r = (v - idx0) % m;
    return (r < 0) ? r + m : r;
}

__device__ __forceinline__ int voxel_index(const int* __restrict__ pts, int b) {
    const int x = redirect(pts[b*3+0],  25, DX);
    const int y = redirect(pts[b*3+1], 225, DY);
    const int z = redirect(pts[b*3+2],  28, DZ);
    return x*(DY*DZ) + y*DZ + z;
}

__global__ void __launch_bounds__(TPB)
ccl_kernel(const float* __restrict__ fixf,
           const float* __restrict__ movf,
           const int*   __restrict__ fp,
           const int*   __restrict__ pp,
           const int*   __restrict__ np_,
           float*       __restrict__ out)
{
    const int tid = blockIdx.x * TPB + threadIdx.x;
    const int b   = tid >> 3;          // point id
    const int sub = tid & (TPP - 1);   // which channel octet

    const int fv = voxel_index(fp,  b);
    const int pv = voxel_index(pp,  b);
    const int nv = voxel_index(np_, b);

    const int cbase = sub * CPT;
    const float* __restrict__ pf = fixf + fv + cbase * PLANE;
    const float* __restrict__ pq = movf + pv + cbase * PLANE;
    const float* __restrict__ pn = movf + nv + cbase * PLANE;

    // 24 fully independent loads per thread (max MLP), then math.
    float fr[CPT], pr[CPT], nr[CPT];
#pragma unroll
    for (int c = 0; c < CPT; c++) {
        fr[c] = __ldg(pf + c * PLANE);
        pr[c] = __ldg(pq + c * PLANE);
        nr[c] = __ldg(pn + c * PLANE);
    }

    float dpos = 0.0f, dneg = 0.0f;
#pragma unroll
    for (int c = 0; c < CPT; c++) {
        const float dp = fr[c] - pr[c];
        const float dn = fr[c] - nr[c];
        dpos = fmaf(dp, dp, dpos);
        dneg = fmaf(dn, dn, dneg);
    }

    // Combine the 8 channel-octets of this point (adjacent lane group of 8).
#pragma unroll
    for (int off = 1; off < TPP; off <<= 1) {
        dpos += __shfl_xor_sync(0xffffffffu, dpos, off);
        dneg += __shfl_xor_sync(0xffffffffu, dneg, off);
    }

    // Per-point loss on the group leader; others contribute 0.
    float loss = 0.0f;
    if (sub == 0) {
        const float lp = dpos * dpos;
        float t = fmaxf(1.0f - sqrtf(dneg), 0.0f);   // MARGIN = 1.0
        loss = lp + t * t;
    }

    // Warp reduce (4 point losses per warp, rest zeros).
#pragma unroll
    for (int off = 16; off > 0; off >>= 1)
        loss += __shfl_xor_sync(0xffffffffu, loss, off);

    __shared__ float s_loss[TPB / 32];
    const int warp = threadIdx.x >> 5;
    const int lane = threadIdx.x & 31;
    if (lane == 0) s_loss[warp] = loss;
    __syncthreads();

    __shared__ bool s_last;
    if (threadIdx.x == 0) {
        float acc = 0.0f;
#pragma unroll
        for (int i = 0; i < TPB / 32; i++) acc += s_loss[i];
        g_partials[blockIdx.x] = acc;
        __threadfence();
        unsigned int prev = atomicAdd(&g_count, 1u);
        s_last = (prev == GRID - 1);
    }
    __syncthreads();

    if (s_last) {
        // Deterministic final reduction over GRID=512 partials.
        __shared__ float s_red[TPB];
        float v = g_partials[threadIdx.x] + g_partials[threadIdx.x + 256];
        s_red[threadIdx.x] = v;
        __syncthreads();
#pragma unroll
        for (int off = 128; off > 0; off >>= 1) {
            if (threadIdx.x < off) s_red[threadIdx.x] += s_red[threadIdx.x + off];
            __syncthreads();
        }
        if (threadIdx.x == 0) {
            // loss = sum / (2 * 2B) * 1e6
            out[0] = s_red[0] * (1000000.0f / (4.0f * (float)NPTS));
            g_count = 0;   // reset for graph replay
        }
    }
}

extern "C" void kernel_launch(void* const* d_in, const int* in_sizes, int n_in,
                              void* d_out, int out_size)
{
    const float* fixf = (const float*)d_in[0];
    const float* movf = (const float*)d_in[1];
    const int*   fp   = (const int*)d_in[2];
    const int*   pp   = (const int*)d_in[3];
    const int*   np_  = (const int*)d_in[4];
    float* out = (float*)d_out;

    ccl_kernel<<<GRID, TPB>>>(fixf, movf, fp, pp, np_, out);
}

// round 5
// speedup vs baseline: 1.2578x; 1.2578x over previous
#include <cuda_runtime.h>

// Problem constants
#define NPTS   16384
#define NCHAN  64
#define DX     100
#define DY     88
#define DZ     80
#define PLANE  (DX*DY*DZ)          // 704000 floats per channel plane

// 2 threads per point -> 32768 threads = 128 blocks * 256 (single wave, all resident)
#define TPB    256
#define GRID   (NPTS * 2 / TPB)    // 128

__device__ float        g_partials[GRID];
__device__ unsigned int g_count = 0;

__device__ __forceinline__ int redirect(int v, int idx0, int m) {
    int r = (v - idx0) % m;
    return (r < 0) ? r + m : r;
}

__device__ __forceinline__ int voxel_index(const int* __restrict__ pts, int b) {
    const int x = redirect(pts[b*3+0],  25, DX);
    const int y = redirect(pts[b*3+1], 225, DY);
    const int z = redirect(pts[b*3+2],  28, DZ);
    return x*(DY*DZ) + y*DZ + z;
}

// Plain (non-nc) global load: avoid the __ldg/texture path in case it is what
// promotes L2<-DRAM fetches to 128B lines. Vanilla LDG.E requests 32B sectors.
__device__ __forceinline__ float plain_load(const float* p) {
    float v;
    asm("ld.global.f32 %0, [%1];" : "=f"(v) : "l"(p));
    return v;
}

__global__ void __launch_bounds__(TPB, 1)
ccl_kernel(const float* fixf,
           const float* movf,
           const int*   __restrict__ fp,
           const int*   __restrict__ pp,
           const int*   __restrict__ np_,
           float*       __restrict__ out)
{
    const int tid  = blockIdx.x * TPB + threadIdx.x;
    const int b    = tid >> 1;          // point id
    const int half = tid & 1;           // channel half: 0 -> [0,32), 1 -> [32,64)

    const int fv = voxel_index(fp,  b);
    const int pv = voxel_index(pp,  b);
    const int nv = voxel_index(np_, b);

    const float* pf = fixf + fv + half * 32 * PLANE;
    const float* pq = movf + pv + half * 32 * PLANE;
    const float* pn = movf + nv + half * 32 * PLANE;

    // Walk 32 channels in (chip-wide, naturally lockstep) order.
    // Unroll 8 -> up to 24 independent loads in flight per thread, and the
    // concurrent channel window stays ~16 planes (~59 MB) < L2 for full reuse.
    float dpos = 0.0f, dneg = 0.0f;
#pragma unroll 8
    for (int c = 0; c < 32; c++) {
        const float f = plain_load(pf + c * PLANE);
        const float p = plain_load(pq + c * PLANE);
        const float n = plain_load(pn + c * PLANE);
        const float dp = f - p;
        const float dn = f - n;
        dpos = fmaf(dp, dp, dpos);
        dneg = fmaf(dn, dn, dneg);
    }

    // Combine the two channel-halves of this point (adjacent lanes).
    dpos += __shfl_xor_sync(0xffffffffu, dpos, 1);
    dneg += __shfl_xor_sync(0xffffffffu, dneg, 1);

    // Per-point loss on the even lane; odd lane contributes 0.
    float loss = 0.0f;
    if (half == 0) {
        const float lp = dpos * dpos;
        float t = fmaxf(1.0f - sqrtf(dneg), 0.0f);   // MARGIN = 1.0
        loss = lp + t * t;
    }

    // Warp reduce the losses (16 points per warp).
#pragma unroll
    for (int off = 16; off > 0; off >>= 1)
        loss += __shfl_xor_sync(0xffffffffu, loss, off);

    __shared__ float s_loss[TPB / 32];
    const int warp = threadIdx.x >> 5;
    const int lane = threadIdx.x & 31;
    if (lane == 0) s_loss[warp] = loss;
    __syncthreads();

    __shared__ bool s_last;
    if (threadIdx.x == 0) {
        float acc = 0.0f;
#pragma unroll
        for (int i = 0; i < TPB / 32; i++) acc += s_loss[i];
        g_partials[blockIdx.x] = acc;
        __threadfence();
        unsigned int prev = atomicAdd(&g_count, 1u);
        s_last = (prev == GRID - 1);
    }
    __syncthreads();

    if (s_last) {
        // Final deterministic reduction over GRID=128 partials.
        __shared__ float s_red[128];
        if (threadIdx.x < 128) s_red[threadIdx.x] = g_partials[threadIdx.x];
        __syncthreads();
#pragma unroll
        for (int off = 64; off > 0; off >>= 1) {
            if (threadIdx.x < off) s_red[threadIdx.x] += s_red[threadIdx.x + off];
            __syncthreads();
        }
        if (threadIdx.x == 0) {
            // loss = sum / (2 * 2B) * 1e6
            out[0] = s_red[0] * (1000000.0f / (4.0f * (float)NPTS));
            g_count = 0;   // reset for graph replay
        }
    }
}

extern "C" void kernel_launch(void* const* d_in, const int* in_sizes, int n_in,
                              void* d_out, int out_size)
{
    const float* fixf = (const float*)d_in[0];
    const float* movf = (const float*)d_in[1];
    const int*   fp   = (const int*)d_in[2];
    const int*   pp   = (const int*)d_in[3];
    const int*   np_  = (const int*)d_in[4];
    float* out = (float*)d_out;

    ccl_kernel<<<GRID, TPB>>>(fixf, movf, fp, pp, np_, out);
}